// round 9
// baseline (speedup 1.0000x reference)
#include <cuda_runtime.h>
#include <cstdint>

#define Dd 128
#define NMAX 50000
#define EMAX 1000000
#define PADW 136   // W smem row stride (words); conflict-free v2 LDS

// Scratch (static device globals -- no allocation allowed)
__device__ float g_u[NMAX * Dd];
__device__ float g_h[NMAX * Dd];
__device__ float g_dinv[NMAX];
__device__ float g_wt[4][Dd * Dd];   // transposed + tf32 + pair-permuted weights [N][K']
__device__ int   g_cnt[NMAX];
__device__ int   g_offs[NMAX];
__device__ int   g_cur[NMAX];
__device__ int   g_csr[EMAX];
__device__ int   g_bsum[256];

__device__ __forceinline__ uint32_t f2tf32(float v) {
    uint32_t r;
    asm("cvt.rna.tf32.f32 %0, %1;" : "=r"(r) : "f"(v));
    return r;
}

__device__ __forceinline__ void mma_tf32(float c[4], uint32_t a0, uint32_t a1,
                                         uint32_t a2, uint32_t a3,
                                         uint32_t b0, uint32_t b1) {
    asm volatile(
        "mma.sync.aligned.m16n8k8.row.col.f32.tf32.tf32.f32 "
        "{%0,%1,%2,%3}, {%4,%5,%6,%7}, {%8,%9}, {%0,%1,%2,%3};"
        : "+f"(c[0]), "+f"(c[1]), "+f"(c[2]), "+f"(c[3])
        : "r"(a0), "r"(a1), "r"(a2), "r"(a3), "r"(b0), "r"(b1));
}

__device__ __forceinline__ int warp_iscan(int v, int lane) {
#pragma unroll
    for (int d = 1; d < 32; d <<= 1) {
        int t = __shfl_up_sync(0xffffffff, v, d);
        if (lane >= d) v += t;
    }
    return v;
}

// ---------------------------------------------------------------------------
// Persistent tf32 mma.sync GEMM, A fragments straight from global (no staging).
//  mode 0: aux=dinv -> C = val*dinv[row]
//  mode 1: aux=bias -> C = relu(val + bias)
//  mode 2: C = val (raw, aux unused)
//  nheads==2: block parity selects (Wt1,aux1,C1)
// ---------------------------------------------------------------------------
__global__ void __launch_bounds__(256, 2) k_mma_gemm(
    const float* __restrict__ A,
    const float* __restrict__ Wt0, const float* __restrict__ aux0, float* __restrict__ C0,
    const float* Wt1, const float* aux1, float* C1,
    int n, int mode, int nheads)
{
    extern __shared__ float sm[];
    uint32_t* Wsu = (uint32_t*)sm;   // [128][PADW]

    int tid  = threadIdx.x;
    int wid  = tid >> 5;
    int lane = tid & 31;

    int ntiles = (n + 127) >> 7;
    int tile0, tstep;
    const float* Wt; const float* aux; float* C;
    if (nheads == 2) {
        int head = blockIdx.x & 1;
        tile0 = blockIdx.x >> 1;
        tstep = gridDim.x >> 1;
        Wt = head ? Wt1 : Wt0; aux = head ? aux1 : aux0; C = head ? C1 : C0;
    } else {
        tile0 = blockIdx.x;
        tstep = gridDim.x;
        Wt = Wt0; aux = aux0; C = C0;
    }

    const uint4* Wt4 = (const uint4*)Wt;
#pragma unroll
    for (int i = 0; i < 16; i++) {
        int f = tid + i * 256;
        int r = f >> 5, j = (f & 31) << 2;
        *(uint4*)(Wsu + r * PADW + j) = Wt4[f];
    }
    __syncthreads();

    int kq  = lane & 3;
    int bn0 = lane >> 2;
    int kq2 = kq << 1;

    for (int tile = tile0; tile < ntiles; tile += tstep) {
        int row0 = tile << 7;
        int r0 = row0 + wid * 16 + (lane >> 2);
        int r1 = r0 + 8;
        bool v0 = r0 < n, v1 = r1 < n;
        const float* a0p = A + (size_t)r0 * 128 + kq;
        const float* a1p = a0p + 8 * 128;

        float c[16][4];
#pragma unroll
        for (int nt = 0; nt < 16; nt++)
#pragma unroll
            for (int q = 0; q < 4; q++) c[nt][q] = 0.0f;

#pragma unroll
        for (int ks = 0; ks < 16; ks++) {
            int kg = ks * 8;
            uint32_t a0 = v0 ? f2tf32(__ldg(a0p + kg))     : 0u;
            uint32_t a1 = v1 ? f2tf32(__ldg(a1p + kg))     : 0u;
            uint32_t a2 = v0 ? f2tf32(__ldg(a0p + kg + 4)) : 0u;
            uint32_t a3 = v1 ? f2tf32(__ldg(a1p + kg + 4)) : 0u;
#pragma unroll
            for (int nt = 0; nt < 16; nt++) {
                uint2 b = *(const uint2*)(Wsu + (nt * 8 + bn0) * PADW + kg + kq2);
                mma_tf32(c[nt], a0, a1, a2, a3, b.x, b.y);
            }
        }

        int cc = kq * 2;
        if (mode == 0) {
            float d0 = v0 ? aux[r0] : 0.0f;
            float d1 = v1 ? aux[r1] : 0.0f;
#pragma unroll
            for (int nt = 0; nt < 16; nt++) {
                int col = nt * 8 + cc;
                if (v0)
                    *(float2*)(C + (size_t)r0 * 128 + col) =
                        make_float2(c[nt][0] * d0, c[nt][1] * d0);
                if (v1)
                    *(float2*)(C + (size_t)r1 * 128 + col) =
                        make_float2(c[nt][2] * d1, c[nt][3] * d1);
            }
        } else if (mode == 1) {
#pragma unroll
            for (int nt = 0; nt < 16; nt++) {
                int col = nt * 8 + cc;
                float2 bb = *(const float2*)(aux + col);
                if (v0)
                    *(float2*)(C + (size_t)r0 * 128 + col) =
                        make_float2(fmaxf(c[nt][0] + bb.x, 0.f), fmaxf(c[nt][1] + bb.y, 0.f));
                if (v1)
                    *(float2*)(C + (size_t)r1 * 128 + col) =
                        make_float2(fmaxf(c[nt][2] + bb.x, 0.f), fmaxf(c[nt][3] + bb.y, 0.f));
            }
        } else {
#pragma unroll
            for (int nt = 0; nt < 16; nt++) {
                int col = nt * 8 + cc;
                if (v0)
                    *(float2*)(C + (size_t)r0 * 128 + col) =
                        make_float2(c[nt][0], c[nt][1]);
                if (v1)
                    *(float2*)(C + (size_t)r1 * 128 + col) =
                        make_float2(c[nt][2], c[nt][3]);
            }
        }
    }
}

// ---------------------------------------------------------------------------
// weight prep only: Wt[w][n][perm(k)] = tf32(W[k][n])
// ---------------------------------------------------------------------------
__global__ void k_prep_w(const float* __restrict__ W0, const float* __restrict__ W1,
                         const float* __restrict__ W2, const float* __restrict__ W3,
                         float* __restrict__ Wt) {
    int i = blockIdx.x * blockDim.x + threadIdx.x;
    if (i >= 4 * Dd * Dd) return;
    int w = i >> 14, r = i & (Dd * Dd - 1);
    const float* W = (w == 0) ? W0 : (w == 1) ? W1 : (w == 2) ? W2 : W3;
    int k = r >> 7, nn = r & 127;
    int kp = (k & ~7) | (2 * (k & 3) + ((k >> 2) & 1));
    ((uint32_t*)Wt)[w * Dd * Dd + nn * Dd + kp] = f2tf32(W[k * Dd + nn]);
}

// ---------------------------------------------------------------------------
// CSR build chain (side stream)
// ---------------------------------------------------------------------------
__global__ void k_zero(int* cnt, int n) {
    int i = blockIdx.x * blockDim.x + threadIdx.x;
    if (i < n) cnt[i] = 0;
}

__global__ void k_hist(const int* __restrict__ dst, int* cnt, int E, int n) {
    int e = blockIdx.x * blockDim.x + threadIdx.x;
    if (e < E) {
        int d = dst[e];
        if ((unsigned)d < (unsigned)n) atomicAdd(&cnt[d], 1);
    }
}

__global__ void k_scan1(const int* __restrict__ cnt, int* offs, int* bsum, int n) {
    __shared__ int ws[8];
    int tid = threadIdx.x, lane = tid & 31, wid = tid >> 5;
    int i = blockIdx.x * 256 + tid;
    int v = (i < n) ? cnt[i] : 0;
    int s = warp_iscan(v, lane);
    if (lane == 31) ws[wid] = s;
    __syncthreads();
    if (wid == 0) {
        int t = (lane < 8) ? ws[lane] : 0;
        t = warp_iscan(t, lane);
        if (lane < 8) ws[lane] = t;
    }
    __syncthreads();
    int base = wid ? ws[wid - 1] : 0;
    if (i < n) offs[i] = base + s - v;
    if (tid == 255) bsum[blockIdx.x] = base + s;
}

// scan2+scan3 merged: each block reduces bsum[0..blockIdx.x) itself
__global__ void k_scan23(int* offs, const int* __restrict__ bsum,
                         const int* __restrict__ cnt, int* cur, float* dinv, int n) {
    __shared__ int ws[8];
    int tid = threadIdx.x, lane = tid & 31, wid = tid >> 5;
    int v = (tid < (int)blockIdx.x) ? bsum[tid] : 0;   // gridDim <= 256
#pragma unroll
    for (int d = 16; d > 0; d >>= 1) v += __shfl_down_sync(0xffffffff, v, d);
    if (lane == 0) ws[wid] = v;
    __syncthreads();
    if (tid == 0) {
        int t = 0;
#pragma unroll
        for (int q = 0; q < 8; q++) t += ws[q];
        ws[0] = t;
    }
    __syncthreads();
    int pre = ws[0];
    int i = blockIdx.x * 256 + tid;
    if (i < n) {
        offs[i] += pre;
        cur[i] = 0;
        dinv[i] = rsqrtf((float)cnt[i] + 1.0f);  // +1 self loop
    }
}

__global__ void k_fill(const int* __restrict__ src, const int* __restrict__ dst,
                       const int* __restrict__ offs, int* cur, int* csr, int E, int n) {
    int e = blockIdx.x * blockDim.x + threadIdx.x;
    if (e < E) {
        int d = dst[e];
        int s = src[e];
        if ((unsigned)d < (unsigned)n && (unsigned)s < (unsigned)n) {
            int p = offs[d] + atomicAdd(&cur[d], 1);
            csr[p] = s;
        }
    }
}

// ---------------------------------------------------------------------------
// CSR gather-reduce + fused epilogue.
//  scale_src=1: u is RAW -> acc = u[i]*dinv[i] + sum u[sj]*dinv[sj]
//  scale_src=0: u pre-scaled -> acc = u[i] + sum u[sj]
//  out = relu?(acc*dinv[i] + b)
// ---------------------------------------------------------------------------
__global__ void __launch_bounds__(256) k_gather(
    const float* __restrict__ u, const int* __restrict__ csr,
    const int* __restrict__ offs, const int* __restrict__ cnt,
    const float* __restrict__ dinv, const float* __restrict__ b,
    float* __restrict__ out, int n, int relu, int scale_src)
{
    int node = (blockIdx.x * 256 + threadIdx.x) >> 5;
    if (node >= n) return;
    int lane = threadIdx.x & 31;
    int j4 = lane << 2;

    float di = dinv[node];
    float self_s = scale_src ? di : 1.0f;

    float4 acc = *(const float4*)(u + (size_t)node * 128 + j4);
    acc.x *= self_s; acc.y *= self_s; acc.z *= self_s; acc.w *= self_s;

    int beg = offs[node];
    int m = cnt[node];

    for (int base = 0; base < m; base += 32) {
        int rem = min(32, m - base);
        int s = 0; float ds = 1.0f;
        if (base + lane < m) {
            s = __ldg(&csr[beg + base + lane]);
            if (scale_src) ds = __ldg(&dinv[s]);
        }
#pragma unroll 4
        for (int j = 0; j < rem; j++) {
            int sj = __shfl_sync(0xffffffff, s, j);
            float dsj = scale_src ? __shfl_sync(0xffffffff, ds, j) : 1.0f;
            float4 v = *(const float4*)(u + (size_t)sj * 128 + j4);
            acc.x = fmaf(v.x, dsj, acc.x);
            acc.y = fmaf(v.y, dsj, acc.y);
            acc.z = fmaf(v.z, dsj, acc.z);
            acc.w = fmaf(v.w, dsj, acc.w);
        }
    }

    float4 bb = *(const float4*)(b + j4);
    acc.x = acc.x * di + bb.x;
    acc.y = acc.y * di + bb.y;
    acc.z = acc.z * di + bb.z;
    acc.w = acc.w * di + bb.w;
    if (relu) {
        acc.x = fmaxf(acc.x, 0.f); acc.y = fmaxf(acc.y, 0.f);
        acc.z = fmaxf(acc.z, 0.f); acc.w = fmaxf(acc.w, 0.f);
    }
    *(float4*)(out + (size_t)node * 128 + j4) = acc;
}

// ---------------------------------------------------------------------------
extern "C" void kernel_launch(void* const* d_in, const int* in_sizes, int n_in,
                              void* d_out, int out_size)
{
    const float* x  = (const float*)d_in[0];
    const int*   ei = (const int*)d_in[1];     // int32 (JAX x64 disabled)
    const float* W0 = (const float*)d_in[2];
    const float* b0 = (const float*)d_in[3];
    const float* W1 = (const float*)d_in[4];
    const float* b1 = (const float*)d_in[5];
    const float* Wv = (const float*)d_in[6];
    const float* bv = (const float*)d_in[7];
    const float* Wt = (const float*)d_in[8];
    const float* bt = (const float*)d_in[9];

    int n = in_sizes[0] / Dd;
    int E = in_sizes[1] / 2;
    if (E > EMAX) E = EMAX;
    const int* srcp = ei;
    const int* dstp = ei + E;

    float* out_h = (float*)d_out;
    float* out_v = out_h + (size_t)n * Dd;
    float* out_t = out_v + (size_t)n * Dd;

    float *u, *h, *dinv, *wt;
    int *cnt, *offs, *cur, *csr, *bsum;
    cudaGetSymbolAddress((void**)&u,    g_u);
    cudaGetSymbolAddress((void**)&h,    g_h);
    cudaGetSymbolAddress((void**)&dinv, g_dinv);
    cudaGetSymbolAddress((void**)&wt,   g_wt);
    cudaGetSymbolAddress((void**)&cnt,  g_cnt);
    cudaGetSymbolAddress((void**)&offs, g_offs);
    cudaGetSymbolAddress((void**)&cur,  g_cur);
    cudaGetSymbolAddress((void**)&csr,  g_csr);
    cudaGetSymbolAddress((void**)&bsum, g_bsum);

    float* wt0 = wt;
    float* wt1 = wt + Dd * Dd;
    float* wtv = wt + 2 * Dd * Dd;
    float* wtt = wt + 3 * Dd * Dd;

    const int SMEM_GEMM = 128 * PADW * 4;   // 69632 bytes (W only)

    static cudaStream_t s1 = nullptr;
    static cudaEvent_t ev0 = nullptr, ev1 = nullptr;
    if (!s1) {
        cudaFuncSetAttribute(k_mma_gemm, cudaFuncAttributeMaxDynamicSharedMemorySize, SMEM_GEMM);
        cudaStreamCreateWithFlags(&s1, cudaStreamNonBlocking);
        cudaEventCreateWithFlags(&ev0, cudaEventDisableTiming);
        cudaEventCreateWithFlags(&ev1, cudaEventDisableTiming);
    }

    int nb256 = (n + 255) / 256;
    int eb256 = (E + 255) / 256;
    int gathB = (n * 32 + 255) / 256;
    int prepB = (4 * Dd * Dd + 255) / 256;
    const int GEMMB = 296;   // persistent: 2 blocks/SM on 148 SMs

    // fork: CSR build on side stream, concurrent with prep_w + GEMM0
    cudaEventRecord(ev0, 0);
    cudaStreamWaitEvent(s1, ev0, 0);
    k_zero <<<nb256, 256, 0, s1>>>(cnt, n);
    k_hist <<<eb256, 256, 0, s1>>>(dstp, cnt, E, n);
    k_scan1<<<nb256, 256, 0, s1>>>(cnt, offs, bsum, n);
    k_scan23<<<nb256, 256, 0, s1>>>(offs, bsum, cnt, cur, dinv, n);
    k_fill <<<eb256, 256, 0, s1>>>(srcp, dstp, offs, cur, csr, E, n);
    cudaEventRecord(ev1, s1);

    // main stream: weights + raw GEMM0 (no dinv dependency)
    k_prep_w<<<prepB, 256>>>(W0, W1, Wv, Wt, wt);
    k_mma_gemm<<<GEMMB, 256, SMEM_GEMM>>>(x, wt0, nullptr, u,
                                          nullptr, nullptr, nullptr, n, 2, 1);

    // join: gather0 needs csr + dinv + u (applies dinv[src] in-loop)
    cudaStreamWaitEvent(0, ev1, 0);
    k_gather<<<gathB, 256>>>(u, csr, offs, cnt, dinv, b0, h, n, 1, 1);

    // layer 1 (pre-scaled u), writes into d_out
    k_mma_gemm<<<GEMMB, 256, SMEM_GEMM>>>(h, wt1, dinv, u,
                                          nullptr, nullptr, nullptr, n, 0, 1);
    k_gather<<<gathB, 256>>>(u, csr, offs, cnt, dinv, b1, out_h, n, 0, 0);

    // both heads, one persistent launch (block parity selects head)
    k_mma_gemm<<<GEMMB, 256, SMEM_GEMM>>>(out_h, wtv, bv, out_v,
                                          wtt, bt, out_t, n, 1, 2);
}

// round 10
// speedup vs baseline: 1.1348x; 1.1348x over previous
#include <cuda_runtime.h>
#include <cstdint>

#define Dd 128
#define NMAX 50000
#define EMAX 1000000
#define PADW 136   // W smem row stride (words); conflict-free per half-warp phase

// Scratch (static device globals -- no allocation allowed)
__device__ float g_u[NMAX * Dd];
__device__ float g_h[NMAX * Dd];
__device__ float g_dinv[NMAX];
__device__ float g_wt[4][Dd * Dd];   // transposed + tf32 + k-permuted weights [N][K']
__device__ int   g_cnt[NMAX];
__device__ int   g_offs[NMAX];
__device__ int   g_cur[NMAX];
__device__ int   g_csr[EMAX];
__device__ int   g_bsum[256];

__device__ __forceinline__ uint32_t f2tf32(float v) {
    uint32_t r;
    asm("cvt.rna.tf32.f32 %0, %1;" : "=r"(r) : "f"(v));
    return r;
}

__device__ __forceinline__ void mma_tf32(float c[4], uint32_t a0, uint32_t a1,
                                         uint32_t a2, uint32_t a3,
                                         uint32_t b0, uint32_t b1) {
    asm volatile(
        "mma.sync.aligned.m16n8k8.row.col.f32.tf32.tf32.f32 "
        "{%0,%1,%2,%3}, {%4,%5,%6,%7}, {%8,%9}, {%0,%1,%2,%3};"
        : "+f"(c[0]), "+f"(c[1]), "+f"(c[2]), "+f"(c[3])
        : "r"(a0), "r"(a1), "r"(a2), "r"(a3), "r"(b0), "r"(b1));
}

__device__ __forceinline__ int warp_iscan(int v, int lane) {
#pragma unroll
    for (int d = 1; d < 32; d <<= 1) {
        int t = __shfl_up_sync(0xffffffff, v, d);
        if (lane >= d) v += t;
    }
    return v;
}

__device__ __forceinline__ float4 ldg4z(const float* p, bool v) {
    if (v) return __ldg((const float4*)p);
    return make_float4(0.f, 0.f, 0.f, 0.f);
}

// ---------------------------------------------------------------------------
// Persistent tf32 mma.sync GEMM. A loaded as float4 per 16-k supergroup:
// lane quad-index kq owns logical k = 16G + 4kq .. +3 (coalesced LDG.128),
// pipelined one supergroup ahead. W smem is pre-permuted to match:
// physical p = (k & ~15) | (s<<3) | (kq<<1) | t  for logical k decomposed as
// kq=(k>>2)&3, s=(k>>1)&1, t=k&1 within its 16-group.
//  mode 0: aux=dinv -> C = val*dinv[row]
//  mode 1: aux=bias -> C = relu(val + bias)
//  nheads==2: block parity selects (Wt1,aux1,C1)
// ---------------------------------------------------------------------------
__global__ void __launch_bounds__(256, 2) k_mma_gemm(
    const float* __restrict__ A,
    const float* __restrict__ Wt0, const float* __restrict__ aux0, float* __restrict__ C0,
    const float* Wt1, const float* aux1, float* C1,
    int n, int mode, int nheads)
{
    extern __shared__ float sm[];
    uint32_t* Wsu = (uint32_t*)sm;   // [128][PADW]

    int tid  = threadIdx.x;
    int wid  = tid >> 5;
    int lane = tid & 31;

    int ntiles = (n + 127) >> 7;
    int tile0, tstep;
    const float* Wt; const float* aux; float* C;
    if (nheads == 2) {
        int head = blockIdx.x & 1;
        tile0 = blockIdx.x >> 1;
        tstep = gridDim.x >> 1;
        Wt = head ? Wt1 : Wt0; aux = head ? aux1 : aux0; C = head ? C1 : C0;
    } else {
        tile0 = blockIdx.x;
        tstep = gridDim.x;
        Wt = Wt0; aux = aux0; C = C0;
    }

    const uint4* Wt4 = (const uint4*)Wt;
#pragma unroll
    for (int i = 0; i < 16; i++) {
        int f = tid + i * 256;
        int r = f >> 5, j = (f & 31) << 2;
        *(uint4*)(Wsu + r * PADW + j) = Wt4[f];
    }
    __syncthreads();

    int kq  = lane & 3;
    int bn0 = lane >> 2;

    for (int tile = tile0; tile < ntiles; tile += tstep) {
        int row0 = tile << 7;
        int r0 = row0 + wid * 16 + (lane >> 2);
        int r1 = r0 + 8;
        bool v0 = r0 < n, v1 = r1 < n;
        const float* a0p = A + (size_t)r0 * 128 + (kq << 2);  // float4 per G at +16G
        const float* a1p = a0p + 8 * 128;

        float c[16][4];
#pragma unroll
        for (int nt = 0; nt < 16; nt++)
#pragma unroll
            for (int q = 0; q < 4; q++) c[nt][q] = 0.0f;

        float4 fA = ldg4z(a0p, v0);
        float4 fB = ldg4z(a1p, v1);

#pragma unroll
        for (int G = 0; G < 8; G++) {
            float4 nA, nB;
            if (G < 7) {
                nA = ldg4z(a0p + (G + 1) * 16, v0);
                nB = ldg4z(a1p + (G + 1) * 16, v1);
            }
            uint32_t a00 = f2tf32(fA.x), a10 = f2tf32(fB.x);
            uint32_t a20 = f2tf32(fA.y), a30 = f2tf32(fB.y);
            uint32_t a01 = f2tf32(fA.z), a11 = f2tf32(fB.z);
            uint32_t a21 = f2tf32(fA.w), a31 = f2tf32(fB.w);
            int gbase = G * 16 + (kq << 1);
#pragma unroll
            for (int nt = 0; nt < 16; nt++) {
                const uint32_t* wr = Wsu + (nt * 8 + bn0) * PADW + gbase;
                uint2 b0 = *(const uint2*)wr;
                uint2 b1 = *(const uint2*)(wr + 8);
                mma_tf32(c[nt], a00, a10, a20, a30, b0.x, b0.y);
                mma_tf32(c[nt], a01, a11, a21, a31, b1.x, b1.y);
            }
            fA = nA; fB = nB;
        }

        int cc = kq * 2;
        if (mode == 0) {
            float d0 = v0 ? aux[r0] : 0.0f;
            float d1 = v1 ? aux[r1] : 0.0f;
#pragma unroll
            for (int nt = 0; nt < 16; nt++) {
                int col = nt * 8 + cc;
                if (v0)
                    *(float2*)(C + (size_t)r0 * 128 + col) =
                        make_float2(c[nt][0] * d0, c[nt][1] * d0);
                if (v1)
                    *(float2*)(C + (size_t)r1 * 128 + col) =
                        make_float2(c[nt][2] * d1, c[nt][3] * d1);
            }
        } else {
#pragma unroll
            for (int nt = 0; nt < 16; nt++) {
                int col = nt * 8 + cc;
                float2 bb = *(const float2*)(aux + col);
                if (v0)
                    *(float2*)(C + (size_t)r0 * 128 + col) =
                        make_float2(fmaxf(c[nt][0] + bb.x, 0.f), fmaxf(c[nt][1] + bb.y, 0.f));
                if (v1)
                    *(float2*)(C + (size_t)r1 * 128 + col) =
                        make_float2(fmaxf(c[nt][2] + bb.x, 0.f), fmaxf(c[nt][3] + bb.y, 0.f));
            }
        }
    }
}

// ---------------------------------------------------------------------------
// prep: Wt[w][n][perm(k)] = tf32(W[k][n]); zero cnt[]
// perm within 16-group: kq=(k>>2)&3, s=(k>>1)&1, t=k&1 -> (s<<3)|(kq<<1)|t
// ---------------------------------------------------------------------------
__global__ void k_prep(const float* __restrict__ W0, const float* __restrict__ W1,
                       const float* __restrict__ W2, const float* __restrict__ W3,
                       float* __restrict__ Wt, int* __restrict__ cnt, int n) {
    int i = blockIdx.x * blockDim.x + threadIdx.x;
    if (i < 4 * Dd * Dd) {
        int w = i >> 14, r = i & (Dd * Dd - 1);
        const float* W = (w == 0) ? W0 : (w == 1) ? W1 : (w == 2) ? W2 : W3;
        int k = r >> 7, nn = r & 127;
        int kp = (k & ~15) | (((k >> 1) & 1) << 3) | (((k >> 2) & 3) << 1) | (k & 1);
        ((uint32_t*)Wt)[w * Dd * Dd + nn * Dd + kp] = f2tf32(W[k * Dd + nn]);
    }
    if (i < n) cnt[i] = 0;
}

// ---------------------------------------------------------------------------
// CSR build
// ---------------------------------------------------------------------------
__global__ void k_hist(const int* __restrict__ dst, int* cnt, int E, int n) {
    int e = blockIdx.x * blockDim.x + threadIdx.x;
    if (e < E) {
        int d = dst[e];
        if ((unsigned)d < (unsigned)n) atomicAdd(&cnt[d], 1);
    }
}

__global__ void k_scan1(const int* __restrict__ cnt, int* offs, int* bsum, int n) {
    __shared__ int ws[8];
    int tid = threadIdx.x, lane = tid & 31, wid = tid >> 5;
    int i = blockIdx.x * 256 + tid;
    int v = (i < n) ? cnt[i] : 0;
    int s = warp_iscan(v, lane);
    if (lane == 31) ws[wid] = s;
    __syncthreads();
    if (wid == 0) {
        int t = (lane < 8) ? ws[lane] : 0;
        t = warp_iscan(t, lane);
        if (lane < 8) ws[lane] = t;
    }
    __syncthreads();
    int base = wid ? ws[wid - 1] : 0;
    if (i < n) offs[i] = base + s - v;
    if (tid == 255) bsum[blockIdx.x] = base + s;
}

// scan2+scan3 merged: each block reduces bsum[0..blockIdx.x) itself
__global__ void k_scan23(int* offs, const int* __restrict__ bsum,
                         const int* __restrict__ cnt, int* cur, float* dinv, int n) {
    __shared__ int ws[8];
    int tid = threadIdx.x, lane = tid & 31, wid = tid >> 5;
    int v = (tid < (int)blockIdx.x) ? bsum[tid] : 0;   // gridDim <= 256
#pragma unroll
    for (int d = 16; d > 0; d >>= 1) v += __shfl_down_sync(0xffffffff, v, d);
    if (lane == 0) ws[wid] = v;
    __syncthreads();
    if (tid == 0) {
        int t = 0;
#pragma unroll
        for (int q = 0; q < 8; q++) t += ws[q];
        ws[0] = t;
    }
    __syncthreads();
    int pre = ws[0];
    int i = blockIdx.x * 256 + tid;
    if (i < n) {
        offs[i] += pre;
        cur[i] = 0;
        dinv[i] = rsqrtf((float)cnt[i] + 1.0f);  // +1 self loop
    }
}

__global__ void k_fill(const int* __restrict__ src, const int* __restrict__ dst,
                       const int* __restrict__ offs, int* cur, int* csr, int E, int n) {
    int e = blockIdx.x * blockDim.x + threadIdx.x;
    if (e < E) {
        int d = dst[e];
        int s = src[e];
        if ((unsigned)d < (unsigned)n && (unsigned)s < (unsigned)n) {
            int p = offs[d] + atomicAdd(&cur[d], 1);
            csr[p] = s;
        }
    }
}

// ---------------------------------------------------------------------------
// CSR gather-reduce + fused epilogue: out = relu?((u[i] + sum u[src])*dinv + b)
// ---------------------------------------------------------------------------
__global__ void __launch_bounds__(256) k_gather(
    const float* __restrict__ u, const int* __restrict__ csr,
    const int* __restrict__ offs, const int* __restrict__ cnt,
    const float* __restrict__ dinv, const float* __restrict__ b,
    float* __restrict__ out, int n, int relu)
{
    int node = (blockIdx.x * 256 + threadIdx.x) >> 5;
    if (node >= n) return;
    int lane = threadIdx.x & 31;
    int j4 = lane << 2;

    float4 acc = *(const float4*)(u + (size_t)node * 128 + j4);
    int beg = offs[node];
    int m = cnt[node];

    for (int base = 0; base < m; base += 32) {
        int rem = min(32, m - base);
        int s = (base + lane < m) ? __ldg(&csr[beg + base + lane]) : 0;
#pragma unroll 4
        for (int j = 0; j < rem; j++) {
            int sj = __shfl_sync(0xffffffff, s, j);
            float4 v = *(const float4*)(u + (size_t)sj * 128 + j4);
            acc.x += v.x; acc.y += v.y; acc.z += v.z; acc.w += v.w;
        }
    }

    float di = dinv[node];
    float4 bb = *(const float4*)(b + j4);
    acc.x = acc.x * di + bb.x;
    acc.y = acc.y * di + bb.y;
    acc.z = acc.z * di + bb.z;
    acc.w = acc.w * di + bb.w;
    if (relu) {
        acc.x = fmaxf(acc.x, 0.f); acc.y = fmaxf(acc.y, 0.f);
        acc.z = fmaxf(acc.z, 0.f); acc.w = fmaxf(acc.w, 0.f);
    }
    *(float4*)(out + (size_t)node * 128 + j4) = acc;
}

// ---------------------------------------------------------------------------
extern "C" void kernel_launch(void* const* d_in, const int* in_sizes, int n_in,
                              void* d_out, int out_size)
{
    const float* x  = (const float*)d_in[0];
    const int*   ei = (const int*)d_in[1];     // int32 (JAX x64 disabled)
    const float* W0 = (const float*)d_in[2];
    const float* b0 = (const float*)d_in[3];
    const float* W1 = (const float*)d_in[4];
    const float* b1 = (const float*)d_in[5];
    const float* Wv = (const float*)d_in[6];
    const float* bv = (const float*)d_in[7];
    const float* Wt = (const float*)d_in[8];
    const float* bt = (const float*)d_in[9];

    int n = in_sizes[0] / Dd;
    int E = in_sizes[1] / 2;
    if (E > EMAX) E = EMAX;
    const int* srcp = ei;
    const int* dstp = ei + E;

    float* out_h = (float*)d_out;
    float* out_v = out_h + (size_t)n * Dd;
    float* out_t = out_v + (size_t)n * Dd;

    float *u, *h, *dinv, *wt;
    int *cnt, *offs, *cur, *csr, *bsum;
    cudaGetSymbolAddress((void**)&u,    g_u);
    cudaGetSymbolAddress((void**)&h,    g_h);
    cudaGetSymbolAddress((void**)&dinv, g_dinv);
    cudaGetSymbolAddress((void**)&wt,   g_wt);
    cudaGetSymbolAddress((void**)&cnt,  g_cnt);
    cudaGetSymbolAddress((void**)&offs, g_offs);
    cudaGetSymbolAddress((void**)&cur,  g_cur);
    cudaGetSymbolAddress((void**)&csr,  g_csr);
    cudaGetSymbolAddress((void**)&bsum, g_bsum);

    float* wt0 = wt;
    float* wt1 = wt + Dd * Dd;
    float* wtv = wt + 2 * Dd * Dd;
    float* wtt = wt + 3 * Dd * Dd;

    const int SMEM_GEMM = 128 * PADW * 4;   // 69632 bytes (W only)

    static bool attr_set = false;
    if (!attr_set) {
        cudaFuncSetAttribute(k_mma_gemm, cudaFuncAttributeMaxDynamicSharedMemorySize, SMEM_GEMM);
        attr_set = true;
    }

    int nb256 = (n + 255) / 256;
    int eb256 = (E + 255) / 256;
    int gathB = (n * 32 + 255) / 256;
    int prepB = (4 * Dd * Dd + 255) / 256;
    const int GEMMB = 296;   // persistent: 2 blocks/SM on 148 SMs

    // prep + CSR build
    k_prep<<<prepB, 256>>>(W0, W1, Wv, Wt, wt, cnt, n);
    k_hist<<<eb256, 256>>>(dstp, cnt, E, n);
    k_scan1<<<nb256, 256>>>(cnt, offs, bsum, n);
    k_scan23<<<nb256, 256>>>(offs, bsum, cnt, cur, dinv, n);
    k_fill<<<eb256, 256>>>(srcp, dstp, offs, cur, csr, E, n);

    // layer 0
    k_mma_gemm<<<GEMMB, 256, SMEM_GEMM>>>(x, wt0, dinv, u,
                                          nullptr, nullptr, nullptr, n, 0, 1);
    k_gather<<<gathB, 256>>>(u, csr, offs, cnt, dinv, b0, h, n, 1);

    // layer 1 (no relu), writes into d_out
    k_mma_gemm<<<GEMMB, 256, SMEM_GEMM>>>(h, wt1, dinv, u,
                                          nullptr, nullptr, nullptr, n, 0, 1);
    k_gather<<<gathB, 256>>>(u, csr, offs, cnt, dinv, b1, out_h, n, 0);

    // both heads, one persistent launch (block parity selects head)
    k_mma_gemm<<<GEMMB, 256, SMEM_GEMM>>>(out_h, wtv, bv, out_v,
                                          wtt, bt, out_t, n, 1, 2);
}